// round 11
// baseline (speedup 1.0000x reference)
#include <cuda_runtime.h>
#include <cuda_fp16.h>

// WarpImageLayer: bilinear warp with flow, border value 0. Fused, phase-split.
// image: (N,C,H,W) fp32, flow: (N,2,H,W) fp32 (normalized; scaled by W/H).
//
// Per block (64x64 tile + 24px margin = 112x112 footprint), TWO phases that
// time-share ONE smem buffer (50176B -> 4 CTAs/SM, occ 50%):
//   Phase A: stage half2(c0,c1) [4B/px], LDS-gather, write out channels 0,1.
//   Phase B: reuse buffer for half(c2) [2B/px], re-read flow (L2 hit),
//            recompute indices, LDS-gather, write channel 2.
// Footprint loaded with clamped indices (border clamp free; unclamped local
// indexing exact). ~2.7% out-of-footprint samples -> fp32 global fallback.
// DRAM ~= 75(img) + 50(flow) + 75(out) = 200MB.

#define N_  32
#define C_  3
#define H_  384
#define W_  512
#define HW_ (H_ * W_)

#define TILE   64
#define MARGIN 24
#define F      (TILE + 2 * MARGIN)   // 112
#define FF     (F * F)               // 12544
#define SMEM_BYTES (FF * 4)          // 50176 -> 4 CTAs/SM

__device__ __forceinline__ unsigned int pack_h2(float a, float b) {
    __half2 h = __floats2half2_rn(a, b);
    return *reinterpret_cast<unsigned int*>(&h);
}

struct Coord {
    float w00, w10, w01, w11;
    int   i00;        // lv*F+lu when in footprint, else -1
    int   u0, v0;     // for fallback
    bool  valid;
};

__device__ __forceinline__ Coord make_coord(
    const float* __restrict__ flbase, int gx, int gy, int fo, int fx0, int fy0)
{
    Coord c;
    float u = (float)gx + __ldg(flbase + fo) * (float)W_;
    float v = (float)gy + __ldg(flbase + HW_ + fo) * (float)H_;
    float u0f = floorf(u);
    float v0f = floorf(v);
    float du = u - u0f;
    float dv = v - v0f;
    c.valid = (u >= 0.0f) && (u <= (float)(W_ - 1)) &&
              (v >= 0.0f) && (v <= (float)(H_ - 1));
    c.w00 = (1.f - du) * (1.f - dv);
    c.w10 = du * (1.f - dv);
    c.w01 = (1.f - du) * dv;
    c.w11 = du * dv;
    c.u0 = (int)u0f;
    c.v0 = (int)v0f;
    int lu = c.u0 - fx0;
    int lv = c.v0 - fy0;
    c.i00 = (lu >= 0 && lu < F - 1 && lv >= 0 && lv < F - 1) ? (lv * F + lu) : -1;
    return c;
}

__global__ __launch_bounds__(256) void warp_fused(
    const float* __restrict__ img,
    const float* __restrict__ flow,
    float* __restrict__ out)
{
    extern __shared__ char smem_raw[];
    unsigned int* plane01 = (unsigned int*)smem_raw;   // phase A: FF x 4B
    __half*       plane2  = (__half*)smem_raw;         // phase B: FF x 2B

    const int tx0 = blockIdx.x * TILE;
    const int ty0 = blockIdx.y * TILE;
    const int n   = blockIdx.z;
    const int fx0 = tx0 - MARGIN;
    const int fy0 = ty0 - MARGIN;

    const float* ib = img + (size_t)n * C_ * HW_;
    const float* flbase = flow + (size_t)n * 2 * HW_;
    float* obase = out + (size_t)n * C_ * HW_;
    const int tid = threadIdx.x;
    const int lx  = tid & (TILE - 1);
    const int ly0 = tid >> 6;
    const int gx  = tx0 + lx;

    // ================= PHASE A: channels 0,1 =================
    #pragma unroll 4
    for (int q = tid; q < FF / 4; q += 256) {
        int e  = q * 4;
        int fr = e / F;
        int fc = e - fr * F;
        int gv = min(max(fy0 + fr, 0), H_ - 1);
        int gu0 = fx0 + fc;

        float4 c0, c1;
        if (gu0 >= 0 && gu0 + 3 <= W_ - 1) {
            int off = gv * W_ + gu0;
            c0 = __ldg((const float4*)(ib + off));
            c1 = __ldg((const float4*)(ib + HW_ + off));
        } else {
            float b0[4], b1[4];
            #pragma unroll
            for (int k = 0; k < 4; k++) {
                int gu = min(max(gu0 + k, 0), W_ - 1);
                int off = gv * W_ + gu;
                b0[k] = __ldg(ib + off);
                b1[k] = __ldg(ib + HW_ + off);
            }
            c0 = make_float4(b0[0], b0[1], b0[2], b0[3]);
            c1 = make_float4(b1[0], b1[1], b1[2], b1[3]);
        }
        uint4 p;
        p.x = pack_h2(c0.x, c1.x);
        p.y = pack_h2(c0.y, c1.y);
        p.z = pack_h2(c0.z, c1.z);
        p.w = pack_h2(c0.w, c1.w);
        *(uint4*)(plane01 + e) = p;
    }
    __syncthreads();

    #pragma unroll 4
    for (int j = 0; j < 16; j++) {
        int gy = ty0 + ly0 + 4 * j;
        int fo = gy * W_ + gx;
        Coord c = make_coord(flbase, gx, gy, fo, fx0, fy0);

        float r0 = 0.f, r1 = 0.f;
        if (c.valid) {
            if (c.i00 >= 0) {
                int i01 = c.i00 + F;
                float2 a = __half22float2(*(__half2*)(plane01 + c.i00));
                float2 b = __half22float2(*(__half2*)(plane01 + c.i00 + 1));
                float2 d = __half22float2(*(__half2*)(plane01 + i01));
                float2 e = __half22float2(*(__half2*)(plane01 + i01 + 1));
                r0 = fmaf(c.w00, a.x, fmaf(c.w10, b.x, fmaf(c.w01, d.x, c.w11 * e.x)));
                r1 = fmaf(c.w00, a.y, fmaf(c.w10, b.y, fmaf(c.w01, d.y, c.w11 * e.y)));
            } else {
                int u0c = min(max(c.u0, 0), W_ - 1);
                int u1c = min(c.u0 + 1, W_ - 1);
                int v0c = min(max(c.v0, 0), H_ - 1);
                int v1c = min(c.v0 + 1, H_ - 1);
                int o00 = v0c * W_ + u0c, o10 = v0c * W_ + u1c;
                int o01 = v1c * W_ + u0c, o11 = v1c * W_ + u1c;
                #pragma unroll
                for (int cc = 0; cc < 2; cc++) {
                    const float* p = ib + cc * HW_;
                    float g = fmaf(c.w00, __ldg(p + o00),
                              fmaf(c.w10, __ldg(p + o10),
                              fmaf(c.w01, __ldg(p + o01),
                                   c.w11 * __ldg(p + o11))));
                    if (cc == 0) r0 = g; else r1 = g;
                }
            }
        }
        obase[fo]       = r0;
        obase[HW_ + fo] = r1;
    }
    __syncthreads();   // all reads of plane01 done before overwrite

    // ================= PHASE B: channel 2 =================
    #pragma unroll 4
    for (int q = tid; q < FF / 4; q += 256) {
        int e  = q * 4;
        int fr = e / F;
        int fc = e - fr * F;
        int gv = min(max(fy0 + fr, 0), H_ - 1);
        int gu0 = fx0 + fc;

        float4 c2;
        if (gu0 >= 0 && gu0 + 3 <= W_ - 1) {
            c2 = __ldg((const float4*)(ib + 2 * HW_ + gv * W_ + gu0));
        } else {
            float b2[4];
            #pragma unroll
            for (int k = 0; k < 4; k++) {
                int gu = min(max(gu0 + k, 0), W_ - 1);
                b2[k] = __ldg(ib + 2 * HW_ + gv * W_ + gu);
            }
            c2 = make_float4(b2[0], b2[1], b2[2], b2[3]);
        }
        uint2 p;
        p.x = pack_h2(c2.x, c2.y);
        p.y = pack_h2(c2.z, c2.w);
        *(uint2*)(plane2 + e) = p;
    }
    __syncthreads();

    #pragma unroll 4
    for (int j = 0; j < 16; j++) {
        int gy = ty0 + ly0 + 4 * j;
        int fo = gy * W_ + gx;
        Coord c = make_coord(flbase, gx, gy, fo, fx0, fy0);

        float r2 = 0.f;
        if (c.valid) {
            if (c.i00 >= 0) {
                int i01 = c.i00 + F;
                float a = __half2float(plane2[c.i00]);
                float b = __half2float(plane2[c.i00 + 1]);
                float d = __half2float(plane2[i01]);
                float e = __half2float(plane2[i01 + 1]);
                r2 = fmaf(c.w00, a, fmaf(c.w10, b, fmaf(c.w01, d, c.w11 * e)));
            } else {
                int u0c = min(max(c.u0, 0), W_ - 1);
                int u1c = min(c.u0 + 1, W_ - 1);
                int v0c = min(max(c.v0, 0), H_ - 1);
                int v1c = min(c.v0 + 1, H_ - 1);
                const float* p = ib + 2 * HW_;
                r2 = fmaf(c.w00, __ldg(p + v0c * W_ + u0c),
                     fmaf(c.w10, __ldg(p + v0c * W_ + u1c),
                     fmaf(c.w01, __ldg(p + v1c * W_ + u0c),
                          c.w11 * __ldg(p + v1c * W_ + u1c))));
            }
        }
        obase[2 * HW_ + fo] = r2;
    }
}

extern "C" void kernel_launch(void* const* d_in, const int* in_sizes, int n_in,
                              void* d_out, int out_size)
{
    const float* img  = (const float*)d_in[0];
    const float* flow = (const float*)d_in[1];
    float*       out  = (float*)d_out;

    cudaFuncSetAttribute(warp_fused,
                         cudaFuncAttributeMaxDynamicSharedMemorySize,
                         SMEM_BYTES);

    dim3 grid(W_ / TILE, H_ / TILE, N_);   // (8, 6, 32)
    warp_fused<<<grid, 256, SMEM_BYTES>>>(img, flow, out);
}

// round 12
// speedup vs baseline: 1.4322x; 1.4322x over previous
#include <cuda_runtime.h>
#include <cuda_fp16.h>

// WarpImageLayer: bilinear warp with flow, border value 0. Fused single kernel.
// Per block: 64x64 output tile + 24px margin = 112x112 footprint staged in smem
// as fp16 planes: half2(c0,c1) [4B/px] + half(c2) [2B/px] = 75264B.
// 512 threads/CTA, 3 CTAs/SM (225.8KB of the 228KB carveout) -> 48 warps/SM.
// Gathers are LDS (no L1tex wavefront cost; i.i.d. flow scatter is served by
// the smem crossbar). Footprint loaded with clamped indices so
// smem[local]==img[clamp(global)] (border clamp free, unclamped local index).
// ~2% out-of-footprint samples -> predicated fp32 global fallback.
// DRAM ~= 75(img, L2-amplified overlap absorbed) + 50(flow) + 75(out) = 200MB.

#define N_  32
#define C_  3
#define H_  384
#define W_  512
#define HW_ (H_ * W_)

#define TILE   64
#define MARGIN 24
#define F      (TILE + 2 * MARGIN)   // 112
#define FF     (F * F)               // 12544
#define SMEM_BYTES (FF * 6)          // 75264
#define NT     512

__device__ __forceinline__ unsigned int pack_h2(float a, float b) {
    __half2 h = __floats2half2_rn(a, b);
    return *reinterpret_cast<unsigned int*>(&h);
}

__global__ __launch_bounds__(NT, 3) void warp_fused(
    const float* __restrict__ img,
    const float* __restrict__ flow,
    float* __restrict__ out)
{
    extern __shared__ char smem_raw[];
    unsigned int* plane01 = (unsigned int*)smem_raw;            // FF x 4B
    __half*       plane2  = (__half*)(smem_raw + FF * 4);       // FF x 2B

    const int tx0 = blockIdx.x * TILE;
    const int ty0 = blockIdx.y * TILE;
    const int n   = blockIdx.z;
    const int fx0 = tx0 - MARGIN;
    const int fy0 = ty0 - MARGIN;

    const float* ib = img + (size_t)n * C_ * HW_;
    const int tid = threadIdx.x;

    // ---- load phase: footprint -> smem planes (quad = 4 consecutive px) ----
    #pragma unroll 4
    for (int q = tid; q < FF / 4; q += NT) {
        int e  = q * 4;
        int fr = e / F;
        int fc = e - fr * F;               // multiple of 4
        int gv = min(max(fy0 + fr, 0), H_ - 1);
        int gu0 = fx0 + fc;                // 4-aligned when in range

        float4 c0, c1, c2;
        if (gu0 >= 0 && gu0 + 3 <= W_ - 1) {
            int off = gv * W_ + gu0;
            c0 = __ldg((const float4*)(ib + off));
            c1 = __ldg((const float4*)(ib + HW_ + off));
            c2 = __ldg((const float4*)(ib + 2 * HW_ + off));
        } else {
            float b0[4], b1[4], b2[4];
            #pragma unroll
            for (int k = 0; k < 4; k++) {
                int gu = min(max(gu0 + k, 0), W_ - 1);
                int off = gv * W_ + gu;
                b0[k] = __ldg(ib + off);
                b1[k] = __ldg(ib + HW_ + off);
                b2[k] = __ldg(ib + 2 * HW_ + off);
            }
            c0 = make_float4(b0[0], b0[1], b0[2], b0[3]);
            c1 = make_float4(b1[0], b1[1], b1[2], b1[3]);
            c2 = make_float4(b2[0], b2[1], b2[2], b2[3]);
        }

        uint4 p01;
        p01.x = pack_h2(c0.x, c1.x);
        p01.y = pack_h2(c0.y, c1.y);
        p01.z = pack_h2(c0.z, c1.z);
        p01.w = pack_h2(c0.w, c1.w);
        *(uint4*)(plane01 + e) = p01;                 // STS.128

        uint2 p2;
        p2.x = pack_h2(c2.x, c2.y);
        p2.y = pack_h2(c2.z, c2.w);
        *(uint2*)(plane2 + e) = p2;                   // STS.64
    }
    __syncthreads();

    // ---- gather phase: 8 output pixels per thread ----
    const int lx  = tid & (TILE - 1);      // 0..63
    const int ly0 = tid >> 6;              // 0..7
    const int gx  = tx0 + lx;
    const float* flbase = flow + (size_t)n * 2 * HW_;
    float* obase = out + (size_t)n * C_ * HW_;

    #pragma unroll 4
    for (int j = 0; j < 8; j++) {
        int ly = ly0 + 8 * j;
        int gy = ty0 + ly;
        int fo = gy * W_ + gx;

        float u = (float)gx + __ldg(flbase + fo) * (float)W_;
        float v = (float)gy + __ldg(flbase + HW_ + fo) * (float)H_;

        float u0f = floorf(u);
        float v0f = floorf(v);
        float du = u - u0f;
        float dv = v - v0f;

        bool valid = (u >= 0.0f) && (u <= (float)(W_ - 1)) &&
                     (v >= 0.0f) && (v <= (float)(H_ - 1));

        float r0 = 0.f, r1 = 0.f, r2 = 0.f;
        if (valid) {
            int u0 = (int)u0f;             // in [0, W-1]
            int v0 = (int)v0f;             // in [0, H-1]
            float w00 = (1.f - du) * (1.f - dv);
            float w10 = du * (1.f - dv);
            float w01 = (1.f - du) * dv;
            float w11 = du * dv;

            int lu = u0 - fx0;
            int lv = v0 - fy0;
            if (lu >= 0 && lu < F - 1 && lv >= 0 && lv < F - 1) {
                int i00 = lv * F + lu;
                int i01 = i00 + F;

                float2 a = __half22float2(*(__half2*)(plane01 + i00));
                float2 b = __half22float2(*(__half2*)(plane01 + i00 + 1));
                float2 c = __half22float2(*(__half2*)(plane01 + i01));
                float2 d = __half22float2(*(__half2*)(plane01 + i01 + 1));

                float a2 = __half2float(plane2[i00]);
                float b2 = __half2float(plane2[i00 + 1]);
                float c2 = __half2float(plane2[i01]);
                float d2 = __half2float(plane2[i01 + 1]);

                r0 = fmaf(w00, a.x, fmaf(w10, b.x, fmaf(w01, c.x, w11 * d.x)));
                r1 = fmaf(w00, a.y, fmaf(w10, b.y, fmaf(w01, c.y, w11 * d.y)));
                r2 = fmaf(w00, a2,  fmaf(w10, b2,  fmaf(w01, c2,  w11 * d2)));
            } else {
                // rare fallback (~2%): fp32 global gather with clamp
                int u0c = min(max(u0, 0), W_ - 1);
                int u1c = min(u0 + 1, W_ - 1);
                int v0c = min(max(v0, 0), H_ - 1);
                int v1c = min(v0 + 1, H_ - 1);
                int o00 = v0c * W_ + u0c, o10 = v0c * W_ + u1c;
                int o01 = v1c * W_ + u0c, o11 = v1c * W_ + u1c;
                #pragma unroll
                for (int cc = 0; cc < C_; cc++) {
                    const float* p = ib + cc * HW_;
                    float g = fmaf(w00, __ldg(p + o00),
                              fmaf(w10, __ldg(p + o10),
                              fmaf(w01, __ldg(p + o01),
                                   w11 * __ldg(p + o11))));
                    if (cc == 0) r0 = g; else if (cc == 1) r1 = g; else r2 = g;
                }
            }
        }

        float* ob = obase + fo;
        ob[0]       = r0;
        ob[HW_]     = r1;
        ob[2 * HW_] = r2;
    }
}

extern "C" void kernel_launch(void* const* d_in, const int* in_sizes, int n_in,
                              void* d_out, int out_size)
{
    const float* img  = (const float*)d_in[0];
    const float* flow = (const float*)d_in[1];
    float*       out  = (float*)d_out;

    cudaFuncSetAttribute(warp_fused,
                         cudaFuncAttributeMaxDynamicSharedMemorySize,
                         SMEM_BYTES);

    dim3 grid(W_ / TILE, H_ / TILE, N_);   // (8, 6, 32)
    warp_fused<<<grid, NT, SMEM_BYTES>>>(img, flow, out);
}